// round 14
// baseline (speedup 1.0000x reference)
#include <cuda_runtime.h>
#include <cstdint>
#include <cstddef>

#define BQ    2048
#define NTOK  98
#define DIMC  256
#define NHEAD 8
#define HD    32
#define NWIN  64
#define QK_SCALE 0.17677669529663687f   // 32^-0.5

#define NN2   (NTOK*NTOK)               // 9604
#define QKV_ELEMS ((size_t)BQ*NHEAD*NTOK*HD)   // 51,380,224
#define BMP   104                       // g_bm pitch (floats), 16B-aligned rows

// ---------------- scratch (static device globals; no cudaMalloc allowed) ----
__device__ float g_q[QKV_ELEMS];
__device__ float g_k[QKV_ELEMS];
__device__ float g_v[QKV_ELEMS];
__device__ float g_o[(size_t)BQ*NTOK*DIMC];    // attn out, tf32-rounded
__device__ float g_bm[(size_t)NWIN*NHEAD*NTOK*BMP];  // bias+mask, padded
__device__ float g_wt_qkv[768*256];     // qkv_w transposed [n][k], tf32-rounded
__device__ float g_wt_proj[256*256];    // proj_w transposed [n][k], tf32-rounded

// ======================= helpers =============================================
__device__ __forceinline__ uint32_t smem_to_u32(const void* p) {
    uint32_t a;
    asm("{ .reg .u64 t; cvta.to.shared.u64 t, %1; cvt.u32.u64 %0, t; }"
        : "=r"(a) : "l"(p));
    return a;
}
__device__ __forceinline__ void cp_async16(uint32_t dst, const void* src) {
    asm volatile("cp.async.cg.shared.global [%0], [%1], 16;"
                 :: "r"(dst), "l"(src) : "memory");
}
#define CP_COMMIT() asm volatile("cp.async.commit_group;" ::: "memory")
#define CP_WAIT(n)  asm volatile("cp.async.wait_group %0;" :: "n"(n) : "memory")

// tf32 warp MMA: D(16x8) += A(16x8) * B(8x8)
__device__ __forceinline__ void mma_tf32(float* d, const uint32_t* a, const uint32_t* b) {
    asm volatile(
        "mma.sync.aligned.m16n8k8.row.col.f32.tf32.tf32.f32 "
        "{%0,%1,%2,%3}, {%4,%5,%6,%7}, {%8,%9}, {%0,%1,%2,%3};"
        : "+f"(d[0]), "+f"(d[1]), "+f"(d[2]), "+f"(d[3])
        : "r"(a[0]), "r"(a[1]), "r"(a[2]), "r"(a[3]), "r"(b[0]), "r"(b[1]));
}

// fp32 -> tf32 round-to-nearest (unbiased).
__device__ __forceinline__ uint32_t to_tf32(float f) {
    uint32_t h;
    asm("cvt.rna.tf32.f32 %0, %1;" : "=r"(h) : "f"(f));
    return h;
}
__device__ __forceinline__ float round_tf32(float f) {
    return __uint_as_float(to_tf32(f));
}

// ---------------- kernel: transpose + tf32-round weights --------------------
__global__ void transpose_w_kernel(const float* __restrict__ W, int N, int which)
{
    __shared__ float t[32][33];
    float* Wt = which ? g_wt_proj : g_wt_qkv;
    int n0 = blockIdx.x * 32, k0 = blockIdx.y * 32;
    int tx = threadIdx.x, ty = threadIdx.y;    // 32 x 8
    #pragma unroll
    for (int j = 0; j < 4; ++j)
        t[ty + j*8][tx] = W[(size_t)(k0 + ty + j*8) * N + n0 + tx];
    __syncthreads();
    #pragma unroll
    for (int j = 0; j < 4; ++j)
        Wt[(size_t)(n0 + ty + j*8) * 256 + k0 + tx] = round_tf32(t[tx][ty + j*8]);
}

// ---------------- kernel: build combined bias+mask per (w,h) -----------------
__global__ void bm_build_kernel(const float* __restrict__ table,
                                const int*   __restrict__ rel,
                                const float* __restrict__ mask)
{
    int wh = blockIdx.x;            // 0..511
    int w = wh >> 3, h = wh & 7;
    float* dst = g_bm + (size_t)wh * (NTOK * BMP);
    const float* mp = mask + (size_t)w * NN2;
    for (int t = threadIdx.x; t < NTOK * BMP; t += blockDim.x) {
        int r = t / BMP, c = t - r * BMP;
        float v = 0.0f;
        if (c < NTOK) {
            int idx = r * NTOK + c;
            v = table[rel[idx] * NHEAD + h] + mp[idx];
        }
        dst[t] = v;
    }
}

// ---------------- 1xTF32 mma.sync GEMM: 128x64 tile, K=256, 3 CTAs/SM -------
// 8 warps in 4(m) x 2(n); warp tile 32x32; acc 32 regs -> higher occupancy.
#define GPITCH 36
#define A_TILE_F (128 * GPITCH)               // 4608 floats
#define B_TILE_F (64 * GPITCH)                // 2304 floats
#define BUF_F  (A_TILE_F + B_TILE_F)          // 6912 floats per buffer
#define GEMM_SMEM (2 * BUF_F * 4)             // 55296 bytes

template<bool IS_QKV>
__global__ void __launch_bounds__(256, 3)
gemm_mma_kernel(const float* __restrict__ Aq,
                const float* __restrict__ bias,
                float* __restrict__ out)
{
    extern __shared__ float smf[];
    uint32_t sb = smem_to_u32(smf);
    const int tid = threadIdx.x;
    const int wid = tid >> 5, lane = tid & 31;
    const int g = lane >> 2, tg = lane & 3;
    const int bm = blockIdx.y * 128;      // m = slow dim
    const int bn = blockIdx.x * 64;       // n = fast dim (A reuse across wave)

    const float* A  = IS_QKV ? Aq : g_o;
    const float* Bt = IS_QKV ? g_wt_qkv : g_wt_proj;
    const int K = 256;

    const int r_  = tid >> 3;
    const int c4_ = tid & 7;

    float acc[2][4][4];
    #pragma unroll
    for (int am = 0; am < 2; ++am)
        #pragma unroll
        for (int an = 0; an < 4; ++an)
            #pragma unroll
            for (int j = 0; j < 4; ++j) acc[am][an][j] = 0.0f;

    auto issue = [&](int c, int buf) {
        int k0 = c * 32;
        uint32_t base = sb + (uint32_t)buf * (BUF_F * 4);
        #pragma unroll
        for (int i = 0; i < 4; ++i) {
            int r = r_ + i * 32;
            cp_async16(base + (uint32_t)(r * GPITCH * 4 + c4_ * 16),
                       A + (size_t)(bm + r) * K + k0 + c4_ * 4);
        }
        #pragma unroll
        for (int i = 0; i < 2; ++i) {
            int r = r_ + i * 32;
            cp_async16(base + (uint32_t)(A_TILE_F * 4 + r * GPITCH * 4 + c4_ * 16),
                       Bt + (size_t)(bn + r) * K + k0 + c4_ * 4);
        }
    };

    issue(0, 0);
    CP_COMMIT();

    const int mw = (wid >> 1) * 32;       // 4 m-tiles of 32
    const int nw = (wid & 1) * 32;        // 2 n-tiles of 32

    #pragma unroll 1
    for (int c = 0; c < 8; ++c) {
        if (c + 1 < 8) { issue(c + 1, (c + 1) & 1); CP_COMMIT(); CP_WAIT(1); }
        else           { CP_WAIT(0); }
        __syncthreads();

        const float* As = smf + (c & 1) * BUF_F;
        const float* Bs = As + A_TILE_F;

        #pragma unroll
        for (int s = 0; s < 4; ++s) {
            int k0 = s * 8 + tg;
            uint32_t b[4][2];
            #pragma unroll
            for (int an = 0; an < 4; ++an) {
                int base = (nw + 8 * an + g) * GPITCH + k0;
                b[an][0] = __float_as_uint(Bs[base]);
                b[an][1] = __float_as_uint(Bs[base + 4]);
            }
            #pragma unroll
            for (int am = 0; am < 2; ++am) {
                int base = (mw + 16 * am + g) * GPITCH + k0;
                uint32_t a[4];
                a[0] = to_tf32(As[base]);
                a[1] = to_tf32(As[base + 8 * GPITCH]);
                a[2] = to_tf32(As[base + 4]);
                a[3] = to_tf32(As[base + 8 * GPITCH + 4]);
                #pragma unroll
                for (int an = 0; an < 4; ++an)
                    mma_tf32(acc[am][an], a, b[an]);
            }
        }
        __syncthreads();
    }

    #pragma unroll
    for (int am = 0; am < 2; ++am) {
        #pragma unroll
        for (int half = 0; half < 2; ++half) {
            int m = bm + mw + 16 * am + g + 8 * half;
            if (IS_QKV) {
                int bwin = m / NTOK;
                int nn   = m - bwin * NTOK;
                #pragma unroll
                for (int an = 0; an < 4; ++an) {
                    int gcol = bn + nw + 8 * an + 2 * tg;
                    int sel  = gcol >> 8;
                    int h    = (gcol >> 5) & 7;
                    int d    = gcol & 31;
                    float* dst = (sel == 0 ? g_q : (sel == 1 ? g_k : g_v))
                               + (((size_t)bwin * NHEAD + h) * NTOK + nn) * HD + d;
                    float sc = (sel == 0) ? QK_SCALE : 1.0f;
                    float2 v;
                    v.x = round_tf32((acc[am][an][2*half+0] + bias[gcol+0]) * sc);
                    v.y = round_tf32((acc[am][an][2*half+1] + bias[gcol+1]) * sc);
                    *(float2*)dst = v;
                }
            } else {
                #pragma unroll
                for (int an = 0; an < 4; ++an) {
                    int gcol = bn + nw + 8 * an + 2 * tg;
                    float2 v;
                    v.x = acc[am][an][2*half+0] + bias[gcol+0];
                    v.y = acc[am][an][2*half+1] + bias[gcol+1];
                    *(float2*)(out + (size_t)m * DIMC + gcol) = v;
                }
            }
        }
    }
}

// ---------------- kernel: mma.sync windowed attention (v4, unchanged) -------
#define ASP 116
#define AQ_OFF 12064
#define AK_OFF 15592
#define AV_OFF 12064
#define ATTN_SMEM_BYTES (19336 * 4)     // 77344 -> 3 CTAs/SM

__global__ void __launch_bounds__(256, 3) attn_mma_kernel(const float* __restrict__ mask)
{
    extern __shared__ float sm[];
    float* Ss = sm;
    float* Qs = sm + AQ_OFF;
    float* Ks = sm + AK_OFF;
    float* Vs = sm + AV_OFF;
    uint32_t sb = smem_to_u32(sm);

    int bid = blockIdx.x;
    int b = bid >> 3, h = bid & 7;
    int w = b & (NWIN - 1);
    int tid = threadIdx.x;
    int wid = tid >> 5, lane = tid & 31;
    int g = lane >> 2, tg = lane & 3;

    const float* qp = g_q + (size_t)bid * (NTOK * HD);
    const float* kp = g_k + (size_t)bid * (NTOK * HD);
    const float* vp = g_v + (size_t)bid * (NTOK * HD);
    const float* bmp = g_bm + (size_t)((w << 3) | h) * (NTOK * BMP);

    // phase 1 (all async): stage bm tile into S, Q and K into their regions
    for (int t = tid; t < NTOK * (BMP / 4); t += 256) {
        int r = t / 26, c4 = t - r * 26;
        cp_async16(sb + (uint32_t)((r * ASP + c4 * 4) * 4),
                   bmp + r * BMP + c4 * 4);
    }
    for (int t = tid; t < 784; t += 256) {
        int i = t >> 3, seg = (t & 7) * 4;
        cp_async16(sb + (uint32_t)((AQ_OFF + i * 36 + seg) * 4), qp + t * 4);
        cp_async16(sb + (uint32_t)((AK_OFF + i * 36 + seg) * 4), kp + t * 4);
    }
    CP_COMMIT();
    CP_WAIT(0);
    __syncthreads();

    // phase 2: S = Q K^T + bm (warps 0..6)
    if (wid < 7) {
        int mrow = wid * 16 + g;
        uint32_t a[4][4];
        #pragma unroll
        for (int kt = 0; kt < 4; ++kt) {
            const float* qb = Qs + mrow*36 + kt*8 + tg;
            a[kt][0] = __float_as_uint(qb[0]);
            a[kt][1] = __float_as_uint(qb[8*36]);
            a[kt][2] = __float_as_uint(qb[4]);
            a[kt][3] = __float_as_uint(qb[8*36 + 4]);
        }
        #pragma unroll 1
        for (int nt = 0; nt < 13; ++nt) {
            float acc[4] = {0.0f, 0.0f, 0.0f, 0.0f};
            #pragma unroll
            for (int kt = 0; kt < 4; ++kt) {
                const float* kb = Ks + (nt*8 + g)*36 + kt*8 + tg;
                uint32_t bb[2];
                bb[0] = __float_as_uint(kb[0]);
                bb[1] = __float_as_uint(kb[4]);
                mma_tf32(acc, a[kt], bb);
            }
            int c0 = nt*8 + 2*tg;
            #pragma unroll
            for (int hh = 0; hh < 2; ++hh) {
                int r = wid*16 + g + 8*hh;
                if (r < 98) {
                    float2 bm2 = *(float2*)&Ss[r*ASP + c0];
                    float2 sv;
                    sv.x = acc[2*hh+0] + bm2.x;
                    sv.y = acc[2*hh+1] + bm2.y;
                    *(float2*)&Ss[r*ASP + c0] = sv;
                }
            }
        }
    }
    __syncthreads();

    // phase 3: V loads async (overlap with softmax); zero pad rows via STS
    for (int t = tid; t < 784; t += 256) {
        int i = t >> 3, seg = (t & 7) * 4;
        cp_async16(sb + (uint32_t)((AV_OFF + i * 40 + seg) * 4), vp + t * 4);
    }
    for (int t = tid; t < 240; t += 256) {
        int r = 98 + t / 40, c = t % 40;
        Vs[r*40 + c] = 0.0f;
    }
    CP_COMMIT();

    // phase 4: quad-parallel softmax (warps 0..6)
    if (wid < 7) {
        int r0 = wid*16 + g;
        int r1 = r0 + 8;
        int r0c = (r0 < 98) ? r0 : 97;
        int r1c = (r1 < 98) ? r1 : 97;
        const float* rowa = Ss + r0c*ASP + 2*tg;
        const float* rowb = Ss + r1c*ASP + 2*tg;

        float va[26], vb[26];
        #pragma unroll
        for (int nt = 0; nt < 13; ++nt) {
            float2 xa = *(const float2*)(rowa + 8*nt);
            float2 xb = *(const float2*)(rowb + 8*nt);
            va[2*nt] = xa.x; va[2*nt+1] = xa.y;
            vb[2*nt] = xb.x; vb[2*nt+1] = xb.y;
        }
        if (tg != 0) {
            va[24] = va[25] = -1e30f;
            vb[24] = vb[25] = -1e30f;
        }
        float ma = va[0], mb = vb[0];
        #pragma unroll
        for (int i = 1; i < 26; ++i) {
            ma = fmaxf(ma, va[i]);
            mb = fmaxf(mb, vb[i]);
        }
        ma = fmaxf(ma, __shfl_xor_sync(0xffffffffu, ma, 1));
        ma = fmaxf(ma, __shfl_xor_sync(0xffffffffu, ma, 2));
        mb = fmaxf(mb, __shfl_xor_sync(0xffffffffu, mb, 1));
        mb = fmaxf(mb, __shfl_xor_sync(0xffffffffu, mb, 2));

        float sa = 0.0f, sb2 = 0.0f;
        #pragma unroll
        for (int i = 0; i < 26; ++i) {
            va[i] = __expf(va[i] - ma); sa  += va[i];
            vb[i] = __expf(vb[i] - mb); sb2 += vb[i];
        }
        sa  += __shfl_xor_sync(0xffffffffu, sa, 1);
        sa  += __shfl_xor_sync(0xffffffffu, sa, 2);
        sb2 += __shfl_xor_sync(0xffffffffu, sb2, 1);
        sb2 += __shfl_xor_sync(0xffffffffu, sb2, 2);
        float ia = 1.0f / sa, ib = 1.0f / sb2;

        if (r0 < 98) {
            float* wrow = Ss + r0*ASP + 2*tg;
            #pragma unroll
            for (int nt = 0; nt < 13; ++nt) {
                if (nt < 12 || tg == 0) {
                    float2 p;
                    p.x = round_tf32(va[2*nt]   * ia);
                    p.y = round_tf32(va[2*nt+1] * ia);
                    *(float2*)(wrow + 8*nt) = p;
                }
            }
        }
        if (r1 < 98) {
            float* wrow = Ss + r1*ASP + 2*tg;
            #pragma unroll
            for (int nt = 0; nt < 13; ++nt) {
                if (nt < 12 || tg == 0) {
                    float2 p;
                    p.x = round_tf32(vb[2*nt]   * ib);
                    p.y = round_tf32(vb[2*nt+1] * ib);
                    *(float2*)(wrow + 8*nt) = p;
                }
            }
        }
    }
    CP_WAIT(0);
    __syncthreads();

    // phase 5: O = P V (warps 0..6)
    if (wid < 7) {
        float oacc[4][4];
        #pragma unroll
        for (int nt = 0; nt < 4; ++nt)
            #pragma unroll
            for (int j = 0; j < 4; ++j) oacc[nt][j] = 0.0f;

        int mrow = wid * 16 + g;
        #pragma unroll 1
        for (int kt = 0; kt < 13; ++kt) {
            const float* pb = Ss + mrow*ASP + kt*8 + tg;
            uint32_t a2[4];
            a2[0] = __float_as_uint(pb[0]);
            a2[1] = __float_as_uint(pb[8*ASP]);
            a2[2] = __float_as_uint(pb[4]);
            a2[3] = __float_as_uint(pb[8*ASP + 4]);
            #pragma unroll
            for (int nt = 0; nt < 4; ++nt) {
                const float* vb2 = Vs + (kt*8 + tg)*40 + nt*8 + g;
                uint32_t bb[2];
                bb[0] = __float_as_uint(vb2[0]);
                bb[1] = __float_as_uint(vb2[4*40]);
                mma_tf32(oacc[nt], a2, bb);
            }
        }

        float* op = g_o + (size_t)b * NTOK * DIMC + h * HD;
        #pragma unroll
        for (int nt = 0; nt < 4; ++nt) {
            int d0 = nt*8 + 2*tg;
            #pragma unroll
            for (int hh = 0; hh < 2; ++hh) {
                int r = wid*16 + g + 8*hh;
                if (r < NTOK) {
                    float2 v;
                    v.x = round_tf32(oacc[nt][2*hh+0]);
                    v.y = round_tf32(oacc[nt][2*hh+1]);
                    *(float2*)(op + (size_t)r * DIMC + d0) = v;
                }
            }
        }
    }
}

// ---------------- launch -----------------------------------------------------
extern "C" void kernel_launch(void* const* d_in, const int* in_sizes, int n_in,
                              void* d_out, int out_size)
{
    const float* x          = (const float*)d_in[0];
    const float* mask       = (const float*)d_in[1];
    const float* qkv_w      = (const float*)d_in[2];
    const float* qkv_b      = (const float*)d_in[3];
    const float* proj_w     = (const float*)d_in[4];
    const float* proj_b     = (const float*)d_in[5];
    const float* bias_table = (const float*)d_in[6];
    const int*   rel_index  = (const int*)d_in[7];
    float* out = (float*)d_out;

    cudaFuncSetAttribute((const void*)gemm_mma_kernel<true>,
                         cudaFuncAttributeMaxDynamicSharedMemorySize, GEMM_SMEM);
    cudaFuncSetAttribute((const void*)gemm_mma_kernel<false>,
                         cudaFuncAttributeMaxDynamicSharedMemorySize, GEMM_SMEM);
    cudaFuncSetAttribute((const void*)attn_mma_kernel,
                         cudaFuncAttributeMaxDynamicSharedMemorySize, ATTN_SMEM_BYTES);

    transpose_w_kernel<<<dim3(24, 8), dim3(32, 8)>>>(qkv_w, 768, 0);
    transpose_w_kernel<<<dim3(8, 8),  dim3(32, 8)>>>(proj_w, 256, 1);
    bm_build_kernel<<<NWIN * NHEAD, 256>>>(bias_table, rel_index, mask);

    // n-blocks fast (x): 12 n-blocks share each A row-block via L2
    gemm_mma_kernel<true><<<dim3(12, 1568), 256, GEMM_SMEM>>>(x, qkv_b, nullptr);

    attn_mma_kernel<<<BQ * NHEAD, 256, ATTN_SMEM_BYTES>>>(mask);

    gemm_mma_kernel<false><<<dim3(4, 1568), 256, GEMM_SMEM>>>(nullptr, proj_b, out);
}

// round 15
// speedup vs baseline: 1.0590x; 1.0590x over previous
#include <cuda_runtime.h>
#include <cstdint>
#include <cstddef>

#define BQ    2048
#define NTOK  98
#define DIMC  256
#define NHEAD 8
#define HD    32
#define NWIN  64
#define QK_SCALE 0.17677669529663687f   // 32^-0.5

#define NN2   (NTOK*NTOK)               // 9604
#define QKV_ELEMS ((size_t)BQ*NHEAD*NTOK*HD)   // 51,380,224
#define BMP   104                       // g_bm pitch (floats)

// ---------------- scratch (static device globals; no cudaMalloc allowed) ----
__device__ float g_q[QKV_ELEMS];
__device__ float g_k[QKV_ELEMS];
__device__ float g_v[QKV_ELEMS];
__device__ float g_o[(size_t)BQ*NTOK*DIMC];    // attn out, tf32-rounded
__device__ float g_bm[(size_t)NWIN*NHEAD*NTOK*BMP];  // bias+mask, padded
__device__ float g_wt_qkv[768*256];     // qkv_w transposed [n][k], tf32-rounded
__device__ float g_wt_proj[256*256];    // proj_w transposed [n][k], tf32-rounded

// ======================= helpers =============================================
__device__ __forceinline__ uint32_t smem_to_u32(const void* p) {
    uint32_t a;
    asm("{ .reg .u64 t; cvta.to.shared.u64 t, %1; cvt.u32.u64 %0, t; }"
        : "=r"(a) : "l"(p));
    return a;
}
__device__ __forceinline__ void cp_async16(uint32_t dst, const void* src) {
    asm volatile("cp.async.cg.shared.global [%0], [%1], 16;"
                 :: "r"(dst), "l"(src) : "memory");
}
#define CP_COMMIT() asm volatile("cp.async.commit_group;" ::: "memory")
#define CP_WAIT(n)  asm volatile("cp.async.wait_group %0;" :: "n"(n) : "memory")

// tf32 warp MMA: D(16x8) += A(16x8) * B(8x8)
__device__ __forceinline__ void mma_tf32(float* d, const uint32_t* a, const uint32_t* b) {
    asm volatile(
        "mma.sync.aligned.m16n8k8.row.col.f32.tf32.tf32.f32 "
        "{%0,%1,%2,%3}, {%4,%5,%6,%7}, {%8,%9}, {%0,%1,%2,%3};"
        : "+f"(d[0]), "+f"(d[1]), "+f"(d[2]), "+f"(d[3])
        : "r"(a[0]), "r"(a[1]), "r"(a[2]), "r"(a[3]), "r"(b[0]), "r"(b[1]));
}

// fp32 -> tf32 round-to-nearest (unbiased).
__device__ __forceinline__ uint32_t to_tf32(float f) {
    uint32_t h;
    asm("cvt.rna.tf32.f32 %0, %1;" : "=r"(h) : "f"(f));
    return h;
}
__device__ __forceinline__ float round_tf32(float f) {
    return __uint_as_float(to_tf32(f));
}

// ---------------- kernel: transpose + tf32-round weights --------------------
__global__ void transpose_w_kernel(const float* __restrict__ W, int N, int which)
{
    __shared__ float t[32][33];
    float* Wt = which ? g_wt_proj : g_wt_qkv;
    int n0 = blockIdx.x * 32, k0 = blockIdx.y * 32;
    int tx = threadIdx.x, ty = threadIdx.y;    // 32 x 8
    #pragma unroll
    for (int j = 0; j < 4; ++j)
        t[ty + j*8][tx] = W[(size_t)(k0 + ty + j*8) * N + n0 + tx];
    __syncthreads();
    #pragma unroll
    for (int j = 0; j < 4; ++j)
        Wt[(size_t)(n0 + ty + j*8) * 256 + k0 + tx] = round_tf32(t[tx][ty + j*8]);
}

// ---------------- kernel: build combined bias+mask per (w,h) -----------------
__global__ void bm_build_kernel(const float* __restrict__ table,
                                const int*   __restrict__ rel,
                                const float* __restrict__ mask)
{
    int wh = blockIdx.x;            // 0..511
    int w = wh >> 3, h = wh & 7;
    float* dst = g_bm + (size_t)wh * (NTOK * BMP);
    const float* mp = mask + (size_t)w * NN2;
    for (int t = threadIdx.x; t < NTOK * BMP; t += blockDim.x) {
        int r = t / BMP, c = t - r * BMP;
        float v = 0.0f;
        if (c < NTOK) {
            int idx = r * NTOK + c;
            v = table[rel[idx] * NHEAD + h] + mp[idx];
        }
        dst[t] = v;
    }
}

// ---------------- 1xTF32 mma.sync GEMM: 128x128 tile, K=256 (R13) -----------
#define GPITCH 36
#define TILE_F (128 * GPITCH)                 // 4608 floats
#define BUF_F  (2 * TILE_F)                   // 9216 floats per buffer
#define GEMM_SMEM (2 * BUF_F * 4)             // 73728 bytes

template<bool IS_QKV>
__global__ void __launch_bounds__(256, 2)
gemm_mma_kernel(const float* __restrict__ Aq,
                const float* __restrict__ bias,
                float* __restrict__ out)
{
    extern __shared__ float smf[];
    uint32_t sb = smem_to_u32(smf);
    const int tid = threadIdx.x;
    const int wid = tid >> 5, lane = tid & 31;
    const int g = lane >> 2, tg = lane & 3;
    const int bm = blockIdx.y * 128;      // m = slow dim
    const int bn = blockIdx.x * 128;      // n = fast dim (A reuse across wave)

    const float* A  = IS_QKV ? Aq : g_o;
    const float* Bt = IS_QKV ? g_wt_qkv : g_wt_proj;
    const int K = 256;

    const int r_  = tid >> 3;
    const int c4_ = tid & 7;

    float acc[4][4][4];
    #pragma unroll
    for (int am = 0; am < 4; ++am)
        #pragma unroll
        for (int an = 0; an < 4; ++an)
            #pragma unroll
            for (int j = 0; j < 4; ++j) acc[am][an][j] = 0.0f;

    auto issue = [&](int c, int buf) {
        int k0 = c * 32;
        uint32_t base = sb + (uint32_t)buf * (BUF_F * 4);
        #pragma unroll
        for (int i = 0; i < 4; ++i) {
            int r = r_ + i * 32;
            cp_async16(base + (uint32_t)(r * GPITCH * 4 + c4_ * 16),
                       A + (size_t)(bm + r) * K + k0 + c4_ * 4);
        }
        #pragma unroll
        for (int i = 0; i < 4; ++i) {
            int r = r_ + i * 32;
            cp_async16(base + (uint32_t)(TILE_F * 4 + r * GPITCH * 4 + c4_ * 16),
                       Bt + (size_t)(bn + r) * K + k0 + c4_ * 4);
        }
    };

    issue(0, 0);
    CP_COMMIT();

    const int mw = (wid >> 2) * 64;
    const int nw = (wid & 3) * 32;

    #pragma unroll 1
    for (int c = 0; c < 8; ++c) {
        if (c + 1 < 8) { issue(c + 1, (c + 1) & 1); CP_COMMIT(); CP_WAIT(1); }
        else           { CP_WAIT(0); }
        __syncthreads();

        const float* As = smf + (c & 1) * BUF_F;
        const float* Bs = As + TILE_F;

        #pragma unroll
        for (int s = 0; s < 4; ++s) {
            int k0 = s * 8 + tg;
            uint32_t b[4][2];
            #pragma unroll
            for (int an = 0; an < 4; ++an) {
                int base = (nw + 8 * an + g) * GPITCH + k0;
                b[an][0] = __float_as_uint(Bs[base]);
                b[an][1] = __float_as_uint(Bs[base + 4]);
            }
            #pragma unroll
            for (int am = 0; am < 4; ++am) {
                int base = (mw + 16 * am + g) * GPITCH + k0;
                uint32_t a[4];
                a[0] = to_tf32(As[base]);
                a[1] = to_tf32(As[base + 8 * GPITCH]);
                a[2] = to_tf32(As[base + 4]);
                a[3] = to_tf32(As[base + 8 * GPITCH + 4]);
                #pragma unroll
                for (int an = 0; an < 4; ++an)
                    mma_tf32(acc[am][an], a, b[an]);
            }
        }
        __syncthreads();
    }

    #pragma unroll
    for (int am = 0; am < 4; ++am) {
        #pragma unroll
        for (int half = 0; half < 2; ++half) {
            int m = bm + mw + 16 * am + g + 8 * half;
            if (IS_QKV) {
                int bwin = m / NTOK;
                int nn   = m - bwin * NTOK;
                #pragma unroll
                for (int an = 0; an < 4; ++an) {
                    int gcol = bn + nw + 8 * an + 2 * tg;
                    int sel  = gcol >> 8;
                    int h    = (gcol >> 5) & 7;
                    int d    = gcol & 31;
                    float* dst = (sel == 0 ? g_q : (sel == 1 ? g_k : g_v))
                               + (((size_t)bwin * NHEAD + h) * NTOK + nn) * HD + d;
                    float sc = (sel == 0) ? QK_SCALE : 1.0f;
                    float2 v;
                    v.x = round_tf32((acc[am][an][2*half+0] + bias[gcol+0]) * sc);
                    v.y = round_tf32((acc[am][an][2*half+1] + bias[gcol+1]) * sc);
                    *(float2*)dst = v;
                }
            } else {
                #pragma unroll
                for (int an = 0; an < 4; ++an) {
                    int gcol = bn + nw + 8 * an + 2 * tg;
                    float2 v;
                    v.x = acc[am][an][2*half+0] + bias[gcol+0];
                    v.y = acc[am][an][2*half+1] + bias[gcol+1];
                    *(float2*)(out + (size_t)m * DIMC + gcol) = v;
                }
            }
        }
    }
}

// ---------------- kernel: mma.sync windowed attention (v5) ------------------
// 4 MMA warps x 2 m-tiles each: B fragments loaded once, used for both tiles.
#define ASP 116
#define AQ_OFF 12064
#define AK_OFF 15592
#define AV_OFF 12064
#define ATTN_SMEM_BYTES (19336 * 4)     // 77344 -> 3 CTAs/SM

__global__ void __launch_bounds__(256, 3) attn_mma_kernel(const float* __restrict__ mask)
{
    extern __shared__ float sm[];
    float* Ss = sm;
    float* Qs = sm + AQ_OFF;
    float* Ks = sm + AK_OFF;
    float* Vs = sm + AV_OFF;
    uint32_t sb = smem_to_u32(sm);

    int bid = blockIdx.x;
    int b = bid >> 3, h = bid & 7;
    int w = b & (NWIN - 1);
    int tid = threadIdx.x;
    int wid = tid >> 5, lane = tid & 31;
    int g = lane >> 2, tg = lane & 3;

    const float* qp = g_q + (size_t)bid * (NTOK * HD);
    const float* kp = g_k + (size_t)bid * (NTOK * HD);
    const float* vp = g_v + (size_t)bid * (NTOK * HD);
    const float* bmp = g_bm + (size_t)((w << 3) | h) * (NTOK * BMP);

    // phase 1 (all async): stage bm tile into S, Q and K into their regions
    for (int t = tid; t < NTOK * (BMP / 4); t += 256) {
        int r = t / 26, c4 = t - r * 26;
        cp_async16(sb + (uint32_t)((r * ASP + c4 * 4) * 4),
                   bmp + r * BMP + c4 * 4);
    }
    for (int t = tid; t < 784; t += 256) {
        int i = t >> 3, seg = (t & 7) * 4;
        cp_async16(sb + (uint32_t)((AQ_OFF + i * 36 + seg) * 4), qp + t * 4);
        cp_async16(sb + (uint32_t)((AK_OFF + i * 36 + seg) * 4), kp + t * 4);
    }
    CP_COMMIT();
    CP_WAIT(0);
    __syncthreads();

    // phase 2: S = Q K^T + bm. Warps 0..3, 2 m-tiles each (tile 7 predicated).
    if (wid < 4) {
        int t0 = 2 * wid, t1 = 2 * wid + 1;
        bool v1 = (t1 < 7);
        int m0 = t0 * 16 + g;
        int m1r = v1 ? (t1 * 16 + g) : m0;    // safe row for loads
        uint32_t a0[4][4], a1[4][4];
        #pragma unroll
        for (int kt = 0; kt < 4; ++kt) {
            const float* q0 = Qs + m0*36 + kt*8 + tg;
            const float* q1 = Qs + m1r*36 + kt*8 + tg;
            a0[kt][0] = __float_as_uint(q0[0]);
            a0[kt][1] = __float_as_uint(q0[8*36]);
            a0[kt][2] = __float_as_uint(q0[4]);
            a0[kt][3] = __float_as_uint(q0[8*36 + 4]);
            a1[kt][0] = __float_as_uint(q1[0]);
            a1[kt][1] = __float_as_uint(q1[8*36]);
            a1[kt][2] = __float_as_uint(q1[4]);
            a1[kt][3] = __float_as_uint(q1[8*36 + 4]);
        }
        #pragma unroll 1
        for (int nt = 0; nt < 13; ++nt) {
            float c0[4] = {0,0,0,0}, c1[4] = {0,0,0,0};
            #pragma unroll
            for (int kt = 0; kt < 4; ++kt) {
                const float* kb = Ks + (nt*8 + g)*36 + kt*8 + tg;
                uint32_t bb[2];
                bb[0] = __float_as_uint(kb[0]);
                bb[1] = __float_as_uint(kb[4]);
                mma_tf32(c0, a0[kt], bb);
                mma_tf32(c1, a1[kt], bb);
            }
            int cc = nt*8 + 2*tg;
            #pragma unroll
            for (int hh = 0; hh < 2; ++hh) {
                int r0 = t0*16 + g + 8*hh;
                if (r0 < 98) {
                    float2 bm2 = *(float2*)&Ss[r0*ASP + cc];
                    float2 sv;
                    sv.x = c0[2*hh+0] + bm2.x;
                    sv.y = c0[2*hh+1] + bm2.y;
                    *(float2*)&Ss[r0*ASP + cc] = sv;
                }
                int r1 = t1*16 + g + 8*hh;
                if (v1 && r1 < 98) {
                    float2 bm2 = *(float2*)&Ss[r1*ASP + cc];
                    float2 sv;
                    sv.x = c1[2*hh+0] + bm2.x;
                    sv.y = c1[2*hh+1] + bm2.y;
                    *(float2*)&Ss[r1*ASP + cc] = sv;
                }
            }
        }
    }
    __syncthreads();

    // phase 3: V loads async (overlap with softmax); zero pad rows via STS
    for (int t = tid; t < 784; t += 256) {
        int i = t >> 3, seg = (t & 7) * 4;
        cp_async16(sb + (uint32_t)((AV_OFF + i * 40 + seg) * 4), vp + t * 4);
    }
    for (int t = tid; t < 240; t += 256) {
        int r = 98 + t / 40, c = t % 40;
        Vs[r*40 + c] = 0.0f;
    }
    CP_COMMIT();

    // phase 4: quad-parallel softmax (warps 0..6)
    if (wid < 7) {
        int r0 = wid*16 + g;
        int r1 = r0 + 8;
        int r0c = (r0 < 98) ? r0 : 97;
        int r1c = (r1 < 98) ? r1 : 97;
        const float* rowa = Ss + r0c*ASP + 2*tg;
        const float* rowb = Ss + r1c*ASP + 2*tg;

        float va[26], vb[26];
        #pragma unroll
        for (int nt = 0; nt < 13; ++nt) {
            float2 xa = *(const float2*)(rowa + 8*nt);
            float2 xb = *(const float2*)(rowb + 8*nt);
            va[2*nt] = xa.x; va[2*nt+1] = xa.y;
            vb[2*nt] = xb.x; vb[2*nt+1] = xb.y;
        }
        if (tg != 0) {
            va[24] = va[25] = -1e30f;
            vb[24] = vb[25] = -1e30f;
        }
        float ma = va[0], mb = vb[0];
        #pragma unroll
        for (int i = 1; i < 26; ++i) {
            ma = fmaxf(ma, va[i]);
            mb = fmaxf(mb, vb[i]);
        }
        ma = fmaxf(ma, __shfl_xor_sync(0xffffffffu, ma, 1));
        ma = fmaxf(ma, __shfl_xor_sync(0xffffffffu, ma, 2));
        mb = fmaxf(mb, __shfl_xor_sync(0xffffffffu, mb, 1));
        mb = fmaxf(mb, __shfl_xor_sync(0xffffffffu, mb, 2));

        float sa = 0.0f, sb2 = 0.0f;
        #pragma unroll
        for (int i = 0; i < 26; ++i) {
            va[i] = __expf(va[i] - ma); sa  += va[i];
            vb[i] = __expf(vb[i] - mb); sb2 += vb[i];
        }
        sa  += __shfl_xor_sync(0xffffffffu, sa, 1);
        sa  += __shfl_xor_sync(0xffffffffu, sa, 2);
        sb2 += __shfl_xor_sync(0xffffffffu, sb2, 1);
        sb2 += __shfl_xor_sync(0xffffffffu, sb2, 2);
        float ia = 1.0f / sa, ib = 1.0f / sb2;

        if (r0 < 98) {
            float* wrow = Ss + r0*ASP + 2*tg;
            #pragma unroll
            for (int nt = 0; nt < 13; ++nt) {
                if (nt < 12 || tg == 0) {
                    float2 p;
                    p.x = round_tf32(va[2*nt]   * ia);
                    p.y = round_tf32(va[2*nt+1] * ia);
                    *(float2*)(wrow + 8*nt) = p;
                }
            }
        }
        if (r1 < 98) {
            float* wrow = Ss + r1*ASP + 2*tg;
            #pragma unroll
            for (int nt = 0; nt < 13; ++nt) {
                if (nt < 12 || tg == 0) {
                    float2 p;
                    p.x = round_tf32(vb[2*nt]   * ib);
                    p.y = round_tf32(vb[2*nt+1] * ib);
                    *(float2*)(wrow + 8*nt) = p;
                }
            }
        }
    }
    CP_WAIT(0);
    __syncthreads();

    // phase 5: O = P V. Warps 0..3, 2 m-tiles each; V fragments shared.
    if (wid < 4) {
        int t0 = 2 * wid, t1 = 2 * wid + 1;
        bool v1 = (t1 < 7);
        int m0 = t0 * 16 + g;
        int m1r = v1 ? (t1 * 16 + g) : m0;
        float o0[4][4], o1[4][4];
        #pragma unroll
        for (int nt = 0; nt < 4; ++nt)
            #pragma unroll
            for (int j = 0; j < 4; ++j) { o0[nt][j] = 0.0f; o1[nt][j] = 0.0f; }

        #pragma unroll 1
        for (int kt = 0; kt < 13; ++kt) {
            const float* p0 = Ss + m0*ASP + kt*8 + tg;
            const float* p1 = Ss + m1r*ASP + kt*8 + tg;
            uint32_t pa[4], pb[4];
            pa[0] = __float_as_uint(p0[0]);
            pa[1] = __float_as_uint(p0[8*ASP]);
            pa[2] = __float_as_uint(p0[4]);
            pa[3] = __float_as_uint(p0[8*ASP + 4]);
            pb[0] = __float_as_uint(p1[0]);
            pb[1] = __float_as_uint(p1[8*ASP]);
            pb[2] = __float_as_uint(p1[4]);
            pb[3] = __float_as_uint(p1[8*ASP + 4]);
            #pragma unroll
            for (int nt = 0; nt < 4; ++nt) {
                const float* vb2 = Vs + (kt*8 + tg)*40 + nt*8 + g;
                uint32_t bb[2];
                bb[0] = __float_as_uint(vb2[0]);
                bb[1] = __float_as_uint(vb2[4*40]);
                mma_tf32(o0[nt], pa, bb);
                mma_tf32(o1[nt], pb, bb);
            }
        }

        float* op = g_o + (size_t)b * NTOK * DIMC + h * HD;
        #pragma unroll
        for (int nt = 0; nt < 4; ++nt) {
            int d0 = nt*8 + 2*tg;
            #pragma unroll
            for (int hh = 0; hh < 2; ++hh) {
                int r0 = t0*16 + g + 8*hh;
                if (r0 < NTOK) {
                    float2 v;
                    v.x = round_tf32(o0[nt][2*hh+0]);
                    v.y = round_tf32(o0[nt][2*hh+1]);
                    *(float2*)(op + (size_t)r0 * DIMC + d0) = v;
                }
                int r1 = t1*16 + g + 8*hh;
                if (v1 && r1 < NTOK) {
                    float2 v;
                    v.x = round_tf32(o1[nt][2*hh+0]);
                    v.y = round_tf32(o1[nt][2*hh+1]);
                    *(float2*)(op + (size_t)r1 * DIMC + d0) = v;
                }
            }
        }
    }
}

// ---------------- launch -----------------------------------------------------
extern "C" void kernel_launch(void* const* d_in, const int* in_sizes, int n_in,
                              void* d_out, int out_size)
{
    const float* x          = (const float*)d_in[0];
    const float* mask       = (const float*)d_in[1];
    const float* qkv_w      = (const float*)d_in[2];
    const float* qkv_b      = (const float*)d_in[3];
    const float* proj_w     = (const float*)d_in[4];
    const float* proj_b     = (const float*)d_in[5];
    const float* bias_table = (const float*)d_in[6];
    const int*   rel_index  = (const int*)d_in[7];
    float* out = (float*)d_out;

    cudaFuncSetAttribute((const void*)gemm_mma_kernel<true>,
                         cudaFuncAttributeMaxDynamicSharedMemorySize, GEMM_SMEM);
    cudaFuncSetAttribute((const void*)gemm_mma_kernel<false>,
                         cudaFuncAttributeMaxDynamicSharedMemorySize, GEMM_SMEM);
    cudaFuncSetAttribute((const void*)attn_mma_kernel,
                         cudaFuncAttributeMaxDynamicSharedMemorySize, ATTN_SMEM_BYTES);

    transpose_w_kernel<<<dim3(24, 8), dim3(32, 8)>>>(qkv_w, 768, 0);
    transpose_w_kernel<<<dim3(8, 8),  dim3(32, 8)>>>(proj_w, 256, 1);
    bm_build_kernel<<<NWIN * NHEAD, 256>>>(bias_table, rel_index, mask);

    gemm_mma_kernel<true><<<dim3(6, 1568), 256, GEMM_SMEM>>>(x, qkv_b, nullptr);

    attn_mma_kernel<<<BQ * NHEAD, 256, ATTN_SMEM_BYTES>>>(mask);

    gemm_mma_kernel<false><<<dim3(2, 1568), 256, GEMM_SMEM>>>(nullptr, proj_b, out);
}